// round 2
// baseline (speedup 1.0000x reference)
#include <cuda_runtime.h>
#include <math.h>

#define Nn   20000
#define Ee   320000
#define Hh   4
#define Dd   128
#define Ll   3
#define Gg   64
#define OUTD 10
#define HD   512      // H*D
#define QKVW 1536     // 3*H*D

// ---------------- scratch (static device memory; no allocation) ----------------
__device__ float g_qkv[(size_t)Nn * QKVW];   // q|k|v per node, row stride 1536
__device__ float g_skip[(size_t)Nn * Dd];
__device__ float g_h0[(size_t)Nn * Dd];
__device__ float g_h1[(size_t)Nn * Dd];
__device__ int   g_cnt[Nn];
__device__ int   g_indptr[Nn + 1];
__device__ int   g_wp[Nn];
__device__ int   g_src[Ee];

// ---------------- CSR build ----------------
__global__ void zero_cnt_kernel() {
    int i = blockIdx.x * blockDim.x + threadIdx.x;
    if (i < Nn) g_cnt[i] = 0;
}

__global__ void hist_kernel(const int* __restrict__ dst) {
    int e = blockIdx.x * blockDim.x + threadIdx.x;
    if (e < Ee) atomicAdd(&g_cnt[dst[e]], 1);
}

__global__ void scan_kernel() {
    __shared__ int ssum[1024];
    const int CH = (Nn + 1023) / 1024;     // 20
    int t = threadIdx.x;
    int base = t * CH;
    int s = 0;
    for (int i = 0; i < CH; i++) {
        int idx = base + i;
        if (idx < Nn) s += g_cnt[idx];
    }
    ssum[t] = s;
    __syncthreads();
    for (int off = 1; off < 1024; off <<= 1) {
        int v = (t >= off) ? ssum[t - off] : 0;
        __syncthreads();
        ssum[t] += v;
        __syncthreads();
    }
    int prefix = (t > 0) ? ssum[t - 1] : 0;
    for (int i = 0; i < CH; i++) {
        int idx = base + i;
        if (idx < Nn) {
            g_indptr[idx] = prefix;
            g_wp[idx] = prefix;
            prefix += g_cnt[idx];
        }
    }
    if (t == 0) g_indptr[Nn] = Ee;
}

__global__ void scatter_kernel(const int* __restrict__ src, const int* __restrict__ dst) {
    int e = blockIdx.x * blockDim.x + threadIdx.x;
    if (e < Ee) {
        int pos = atomicAdd(&g_wp[dst[e]], 1);
        g_src[pos] = src[e];
    }
}

// ---------------- fp32 tiled GEMM: Y[r, coff+c] = X[r,:] @ W[:,c] + bias[c] ----------------
// X: [nrows,128] row-major, W: [128,C] row-major, Y row stride ldy.
#define BM 64
#define BN 64
#define BK 32
__global__ __launch_bounds__(256) void gemm_kernel(
    const float* __restrict__ X, const float* __restrict__ W,
    const float* __restrict__ bias, float* __restrict__ Y,
    int nrows, int C, int ldy, int coff)
{
    __shared__ float As[BK][BM];
    __shared__ float Bs[BK][BN];
    int bm = blockIdx.x * BM;
    int bn = blockIdx.y * BN;
    int tid = threadIdx.x;
    int tx = tid & 15;
    int ty = tid >> 4;

    float acc[4][4] = {};

    for (int k0 = 0; k0 < Dd; k0 += BK) {
        // A tile: 64 rows x 32 cols = 512 float4, 2 per thread (transpose into As[k][m])
        #pragma unroll
        for (int i = 0; i < 2; i++) {
            int f = tid * 2 + i;
            int r = f >> 3, c4 = f & 7;
            float4 v = make_float4(0.f, 0.f, 0.f, 0.f);
            int grow = bm + r;
            if (grow < nrows) v = *(const float4*)(X + (size_t)grow * Dd + k0 + c4 * 4);
            As[c4 * 4 + 0][r] = v.x;
            As[c4 * 4 + 1][r] = v.y;
            As[c4 * 4 + 2][r] = v.z;
            As[c4 * 4 + 3][r] = v.w;
        }
        // B tile: 32 rows x 64 cols = 512 float4
        #pragma unroll
        for (int i = 0; i < 2; i++) {
            int f = tid * 2 + i;
            int r = f >> 4, c4 = f & 15;
            float4 v = *(const float4*)(W + (size_t)(k0 + r) * C + bn + c4 * 4);
            *(float4*)&Bs[r][c4 * 4] = v;
        }
        __syncthreads();
        #pragma unroll
        for (int k = 0; k < BK; k++) {
            float4 a = *(const float4*)&As[k][ty * 4];
            float4 b = *(const float4*)&Bs[k][tx * 4];
            acc[0][0] += a.x * b.x; acc[0][1] += a.x * b.y; acc[0][2] += a.x * b.z; acc[0][3] += a.x * b.w;
            acc[1][0] += a.y * b.x; acc[1][1] += a.y * b.y; acc[1][2] += a.y * b.z; acc[1][3] += a.y * b.w;
            acc[2][0] += a.z * b.x; acc[2][1] += a.z * b.y; acc[2][2] += a.z * b.z; acc[2][3] += a.z * b.w;
            acc[3][0] += a.w * b.x; acc[3][1] += a.w * b.y; acc[3][2] += a.w * b.z; acc[3][3] += a.w * b.w;
        }
        __syncthreads();
    }

    float4 bv = *(const float4*)(bias + bn + tx * 4);
    #pragma unroll
    for (int i = 0; i < 4; i++) {
        int grow = bm + ty * 4 + i;
        if (grow < nrows) {
            float4 o;
            o.x = acc[i][0] + bv.x;
            o.y = acc[i][1] + bv.y;
            o.z = acc[i][2] + bv.z;
            o.w = acc[i][3] + bv.w;
            *(float4*)(Y + (size_t)grow * ldy + coff + bn + tx * 4) = o;
        }
    }
}

// ---------------- attention: one warp per destination node, online softmax ----------------
__global__ __launch_bounds__(256) void attn_kernel(
    const float* __restrict__ qkv, const float* __restrict__ skip,
    float* __restrict__ hout)
{
    int warp = (blockIdx.x * blockDim.x + threadIdx.x) >> 5;
    int lane = threadIdx.x & 31;
    if (warp >= Nn) return;

    const float scale = 0.088388347648318447f;  // 1/sqrt(128)
    const float* qrow = qkv + (size_t)warp * QKVW;

    float4 q[Hh];
    #pragma unroll
    for (int h = 0; h < Hh; h++)
        q[h] = *(const float4*)(qrow + h * Dd + lane * 4);

    float m[Hh], l[Hh];
    float4 acc[Hh];
    #pragma unroll
    for (int h = 0; h < Hh; h++) {
        m[h] = -INFINITY;
        l[h] = 0.f;
        acc[h] = make_float4(0.f, 0.f, 0.f, 0.f);
    }

    int beg = g_indptr[warp];
    int end = g_indptr[warp + 1];
    for (int e = beg; e < end; e++) {
        int s = g_src[e];
        const float* krow = qkv + (size_t)s * QKVW + HD;
        float p[Hh];
        #pragma unroll
        for (int h = 0; h < Hh; h++) {
            float4 kv = *(const float4*)(krow + h * Dd + lane * 4);
            p[h] = q[h].x * kv.x + q[h].y * kv.y + q[h].z * kv.z + q[h].w * kv.w;
        }
        #pragma unroll
        for (int off = 16; off; off >>= 1) {
            p[0] += __shfl_xor_sync(0xffffffffu, p[0], off);
            p[1] += __shfl_xor_sync(0xffffffffu, p[1], off);
            p[2] += __shfl_xor_sync(0xffffffffu, p[2], off);
            p[3] += __shfl_xor_sync(0xffffffffu, p[3], off);
        }
        const float* vrow = qkv + (size_t)s * QKVW + 2 * HD;
        #pragma unroll
        for (int h = 0; h < Hh; h++) {
            float sc = p[h] * scale;
            float mnew = fmaxf(m[h], sc);
            float corr = __expf(m[h] - mnew);   // exp(-inf)=0 on first edge
            float w = __expf(sc - mnew);
            l[h] = l[h] * corr + w;
            float4 vv = *(const float4*)(vrow + h * Dd + lane * 4);
            acc[h].x = acc[h].x * corr + w * vv.x;
            acc[h].y = acc[h].y * corr + w * vv.y;
            acc[h].z = acc[h].z * corr + w * vv.z;
            acc[h].w = acc[h].w * corr + w * vv.w;
            m[h] = mnew;
        }
    }

    float inv[Hh];
    #pragma unroll
    for (int h = 0; h < Hh; h++) inv[h] = (l[h] > 0.f) ? (1.f / l[h]) : 0.f;

    float4 out;
    out.x = 0.25f * (acc[0].x * inv[0] + acc[1].x * inv[1] + acc[2].x * inv[2] + acc[3].x * inv[3]);
    out.y = 0.25f * (acc[0].y * inv[0] + acc[1].y * inv[1] + acc[2].y * inv[2] + acc[3].y * inv[3]);
    out.z = 0.25f * (acc[0].z * inv[0] + acc[1].z * inv[1] + acc[2].z * inv[2] + acc[3].z * inv[3]);
    out.w = 0.25f * (acc[0].w * inv[0] + acc[1].w * inv[1] + acc[2].w * inv[2] + acc[3].w * inv[3]);

    float4 sk = *(const float4*)(skip + (size_t)warp * Dd + lane * 4);
    out.x = fmaxf(out.x + sk.x, 0.f);
    out.y = fmaxf(out.y + sk.y, 0.f);
    out.z = fmaxf(out.z + sk.z, 0.f);
    out.w = fmaxf(out.w + sk.w, 0.f);
    *(float4*)(hout + (size_t)warp * Dd + lane * 4) = out;
}

// ---------------- global mean pool (batch sorted) + classifier ----------------
__device__ __forceinline__ int lower_bound_dev(const int* a, int n, int key) {
    int lo = 0, hi = n;
    while (lo < hi) {
        int mid = (lo + hi) >> 1;
        if (a[mid] < key) lo = mid + 1; else hi = mid;
    }
    return lo;
}

__global__ __launch_bounds__(128) void pool_classify_kernel(
    const float* __restrict__ hfin, const int* __restrict__ batch,
    const float* __restrict__ Wc, const float* __restrict__ bc,
    float* __restrict__ out)
{
    int g = blockIdx.x;
    int t = threadIdx.x;  // 128 threads, one per feature dim
    int start = lower_bound_dev(batch, Nn, g);
    int end = lower_bound_dev(batch, Nn, g + 1);

    __shared__ float pooled[Dd];
    float s = 0.f;
    for (int node = start; node < end; node++)
        s += hfin[(size_t)node * Dd + t];
    int cnt = end - start;
    pooled[t] = s / (float)(cnt > 0 ? cnt : 1);
    __syncthreads();

    if (t < OUTD) {
        float o = bc[t];
        #pragma unroll 8
        for (int d = 0; d < Dd; d++)
            o += pooled[d] * Wc[d * OUTD + t];
        out[g * OUTD + t] = o;
    }
}

// ---------------- launch ----------------
extern "C" void kernel_launch(void* const* d_in, const int* in_sizes, int n_in,
                              void* d_out, int out_size)
{
    const float* x     = (const float*)d_in[0];
    const int*   ei    = (const int*)d_in[1];
    const int*   batch = (const int*)d_in[2];
    const float* Wq    = (const float*)d_in[3];
    const float* bq    = (const float*)d_in[4];
    const float* Wk    = (const float*)d_in[5];
    const float* bk    = (const float*)d_in[6];
    const float* Wv    = (const float*)d_in[7];
    const float* bv    = (const float*)d_in[8];
    const float* Wsk   = (const float*)d_in[9];
    const float* bsk   = (const float*)d_in[10];
    const float* Wc    = (const float*)d_in[11];
    const float* bc    = (const float*)d_in[12];

    const int* src = ei;
    const int* dst = ei + Ee;

    float *qkv_p, *skip_p, *h0_p, *h1_p;
    cudaGetSymbolAddress((void**)&qkv_p,  g_qkv);
    cudaGetSymbolAddress((void**)&skip_p, g_skip);
    cudaGetSymbolAddress((void**)&h0_p,   g_h0);
    cudaGetSymbolAddress((void**)&h1_p,   g_h1);

    // CSR by destination
    zero_cnt_kernel<<<(Nn + 255) / 256, 256>>>();
    hist_kernel<<<(Ee + 255) / 256, 256>>>(dst);
    scan_kernel<<<1, 1024>>>();
    scatter_kernel<<<(Ee + 255) / 256, 256>>>(src, dst);

    const int gm = (Nn + BM - 1) / BM;   // 313
    const float* hcur = x;
    for (int l = 0; l < Ll; l++) {
        gemm_kernel<<<dim3(gm, HD / BN), 256>>>(hcur, Wq + (size_t)l * Dd * HD, bq + (size_t)l * HD,
                                                qkv_p, Nn, HD, QKVW, 0);
        gemm_kernel<<<dim3(gm, HD / BN), 256>>>(hcur, Wk + (size_t)l * Dd * HD, bk + (size_t)l * HD,
                                                qkv_p, Nn, HD, QKVW, HD);
        gemm_kernel<<<dim3(gm, HD / BN), 256>>>(hcur, Wv + (size_t)l * Dd * HD, bv + (size_t)l * HD,
                                                qkv_p, Nn, HD, QKVW, 2 * HD);
        gemm_kernel<<<dim3(gm, Dd / BN), 256>>>(hcur, Wsk + (size_t)l * Dd * Dd, bsk + (size_t)l * Dd,
                                                skip_p, Nn, Dd, Dd, 0);
        float* hnext = (l & 1) ? h1_p : h0_p;
        attn_kernel<<<(Nn * 32 + 255) / 256, 256>>>(qkv_p, skip_p, hnext);
        hcur = hnext;
    }

    pool_classify_kernel<<<Gg, 128>>>(hcur, batch, Wc, bc, (float*)d_out);
}